// round 4
// baseline (speedup 1.0000x reference)
#include <cuda_runtime.h>
#include <cstdint>

#define FULLMASK 0xffffffffu

static constexpr int BB   = 16;
static constexpr int NN   = 4096;
static constexpr int CC   = 64;
static constexpr int MM   = 1024;
static constexpr int KNN  = 32;

typedef unsigned long long u64;

// --------------------------------------------------------------------------
// Scratch (device globals; no runtime allocation allowed)
// --------------------------------------------------------------------------
__device__ int      g_cidx[BB * MM];
__device__ float    g_h1f[(size_t)BB * NN * 64];   // W1_feat @ features, [b][n][64]
__device__ unsigned g_pairs[BB * MM * KNN];        // packed (b<<22)|(m<<12)|n
__device__ int      g_pcount;
// folded MLP constants (computed in k1 spare block)
__device__ float4   g_l1w[64];     // (w1x*s1, w1y*s1, w1z*s1, s1)
__device__ float4   g_l1c[16];     // c1[o] = b1*s1+be1, packed 4-wide
__device__ float4   g_c2[16];      // c2[o] = b2*s2+be2
__device__ float4   g_c3[32];      // c3[o] = b3*s3+be3

// --------------------------------------------------------------------------
// Packed f32x2 helpers (IEEE rn, bit-identical to scalar rn ops)
// --------------------------------------------------------------------------
__device__ __forceinline__ u64 pk2(float lo, float hi) {
    u64 r; asm("mov.b64 %0,{%1,%2};" : "=l"(r) : "f"(lo), "f"(hi)); return r;
}
__device__ __forceinline__ void upk2(u64 v, float& lo, float& hi) {
    asm("mov.b64 {%0,%1},%2;" : "=f"(lo), "=f"(hi) : "l"(v));
}
__device__ __forceinline__ u64 add2(u64 a, u64 b) {
    u64 r; asm("add.rn.f32x2 %0,%1,%2;" : "=l"(r) : "l"(a), "l"(b)); return r;
}
__device__ __forceinline__ u64 mul2(u64 a, u64 b) {
    u64 r; asm("mul.rn.f32x2 %0,%1,%2;" : "=l"(r) : "l"(a), "l"(b)); return r;
}
__device__ __forceinline__ u64 fma2p(u64 a, u64 b, u64 c) {
    u64 r; asm("fma.rn.f32x2 %0,%1,%2,%3;" : "=l"(r) : "l"(a), "l"(b), "l"(c)); return r;
}
__device__ __forceinline__ void lds128(u64& a, u64& b, unsigned addr) {
    asm volatile("ld.shared.v2.u64 {%0,%1},[%2];" : "=l"(a), "=l"(b) : "r"(addr));
}

// --------------------------------------------------------------------------
// Kernel 1: blocks 0..15 -> FPS; blocks 16..271 -> h1f + zero + constants
// dynamic smem: 16KB (h1f weight tile; FPS ignores it)
// --------------------------------------------------------------------------
__global__ void __launch_bounds__(256) k_fps_h1f(
    const float* __restrict__ points,
    const float* __restrict__ features,
    const float* __restrict__ w1, const float* __restrict__ b1,
    const float* __restrict__ g1, const float* __restrict__ be1,
    const float* __restrict__ b2, const float* __restrict__ g2,
    const float* __restrict__ be2,
    const float* __restrict__ b3, const float* __restrict__ g3,
    const float* __restrict__ be3,
    float* __restrict__ d_out)
{
    extern __shared__ float smf[];
    const int t = threadIdx.x;

    if (blockIdx.x < BB) {
        // ------------------------- FPS -------------------------
        __shared__ u64    skey[2][8];
        __shared__ float4 scrd[2][8];

        const int b = blockIdx.x;
        const float* px = points + (size_t)b * 3 * NN;

        u64 x2[8], y2[8], z2[8];
        float dl[8], dh[8];
#pragma unroll
        for (int q = 0; q < 8; q++) {
            int pi = (q << 8) + t;
            x2[q] = ((const u64*)px)[pi];
            y2[q] = ((const u64*)(px + NN))[pi];
            z2[q] = ((const u64*)(px + 2 * NN))[pi];
            dl[q] = 1e10f; dh[q] = 1e10f;
        }
        float lx = __ldg(px), ly = __ldg(px + NN), lz = __ldg(px + 2 * NN);
        if (t == 0) {
            g_cidx[b * MM] = 0;
            d_out[(size_t)b * 3 * MM]          = lx;
            d_out[(size_t)b * 3 * MM + MM]     = ly;
            d_out[(size_t)b * 3 * MM + 2 * MM] = lz;
        }
        const int wid = t >> 5;

        for (int m = 1; m < MM; m++) {
            const int buf = m & 1;
            const u64 nx = pk2(-lx, -lx), ny = pk2(-ly, -ly), nz = pk2(-lz, -lz);
            float vq[8];
#pragma unroll
            for (int q = 0; q < 8; q++) {
                u64 dx = add2(x2[q], nx);
                u64 dy = add2(y2[q], ny);
                u64 dz = add2(z2[q], nz);
                u64 d2 = add2(add2(mul2(dx, dx), mul2(dy, dy)), mul2(dz, dz));
                float a, c; upk2(d2, a, c);
                dl[q] = fminf(dl[q], a);
                dh[q] = fminf(dh[q], c);
                vq[q] = fmaxf(dl[q], dh[q]);
            }
            // per-thread max tree (depth 3)
            float v0 = fmaxf(vq[0], vq[1]), v1 = fmaxf(vq[2], vq[3]);
            float v2 = fmaxf(vq[4], vq[5]), v3 = fmaxf(vq[6], vq[7]);
            float vm = fmaxf(fmaxf(v0, v1), fmaxf(v2, v3));
            // warp max value (non-negative f32 -> u32 ordering)
            unsigned bu = __reduce_max_sync(FULLMASK, __float_as_uint(vm));
            // min matching index via parallel tree (exact jnp.argmax tie-break)
            unsigned c16[16];
#pragma unroll
            for (int q = 0; q < 8; q++) {
                unsigned i0 = (q << 9) + (t << 1);
                c16[2 * q]     = (__float_as_uint(dl[q]) == bu) ? i0     : 0xFFFFFFFFu;
                c16[2 * q + 1] = (__float_as_uint(dh[q]) == bu) ? i0 + 1 : 0xFFFFFFFFu;
            }
#pragma unroll
            for (int s = 8; s; s >>= 1)
#pragma unroll
                for (int j = 0; j < s; j++) c16[j] = min(c16[j], c16[j + s]);
            unsigned wi = __reduce_min_sync(FULLMASK, c16[0]);
            if (c16[0] == wi) {            // unique owner lane of index wi
                float wx = __ldg(px + wi);
                float wy = __ldg(px + NN + wi);
                float wz = __ldg(px + 2 * NN + wi);
                skey[buf][wid] = ((u64)bu << 32) | (u64)(~wi);
                scrd[buf][wid] = make_float4(wx, wy, wz, 0.0f);
            }
            __syncthreads();
            u64 k[8]; float4 cd[8];
#pragma unroll
            for (int i = 0; i < 8; i++) { k[i] = skey[buf][i]; cd[i] = scrd[buf][i]; }
#pragma unroll
            for (int s = 4; s; s >>= 1)
#pragma unroll
                for (int j = 0; j < s; j++)
                    if (k[j + s] > k[j]) { k[j] = k[j + s]; cd[j] = cd[j + s]; }
            lx = cd[0].x; ly = cd[0].y; lz = cd[0].z;
            if (t == 0) {
                g_cidx[b * MM + m] = (int)(~(unsigned)k[0]);
                d_out[(size_t)b * 3 * MM + m]          = lx;
                d_out[(size_t)b * 3 * MM + MM + m]     = ly;
                d_out[(size_t)b * 3 * MM + 2 * MM + m] = lz;
            }
        }
    } else {
        // ---------- h1f precompute + output zero + constants ----------
        const int job = blockIdx.x - BB;       // 0..255
        const int b   = job >> 4;
        const int n   = ((job & 15) << 8) + t;
        const float inv = 1.0f / sqrtf(1.0f + 1e-5f);

        if (job == 0) {
            if (t == 0) g_pcount = 0;
            if (t < 64) {
                float s1 = g1[t] * inv;
                g_l1w[t] = make_float4(w1[t * 67] * s1, w1[t * 67 + 1] * s1,
                                       w1[t * 67 + 2] * s1, s1);
                ((float*)g_l1c)[t] = fmaf(b1[t], s1, be1[t]);
                float s2 = g2[t] * inv;
                ((float*)g_c2)[t] = fmaf(b2[t], s2, be2[t]);
            } else if (t < 192) {
                int o = t - 64;
                float s3 = g3[o] * inv;
                ((float*)g_c3)[o] = fmaf(b3[o], s3, be3[o]);
            }
        }
        // zero feature output region [BB*128*MM floats]
        {
            float* ofeat = d_out + (size_t)BB * 3 * MM;
            int base = job * 256 + t;          // 0..65535
            for (int r = 0; r < 32; r++)
                ofeat[(size_t)base * 32 + r] = 0.0f;
        }

        for (int i = t; i < 64 * 64; i += 256) {
            int c = i >> 6, o = i & 63;
            smf[c * 64 + o] = w1[o * 67 + 3 + c];
        }
        __syncthreads();

        u64 acc[32];
#pragma unroll
        for (int k = 0; k < 32; k++) acc[k] = 0ULL;

        const float* fb = features + (size_t)b * CC * NN + n;
        unsigned wbase = (unsigned)__cvta_generic_to_shared(smf);
#pragma unroll
        for (int c = 0; c < 64; c++) {
            float f = fb[c * NN];
            u64 vv = pk2(f, f);
            unsigned addr = wbase + c * 256;
#pragma unroll
            for (int k = 0; k < 16; k++) {
                u64 wa, wb; lds128(wa, wb, addr + k * 16);
                acc[2 * k]     = fma2p(wa, vv, acc[2 * k]);
                acc[2 * k + 1] = fma2p(wb, vv, acc[2 * k + 1]);
            }
        }
        ulonglong2* op = (ulonglong2*)(g_h1f + ((size_t)b * NN + n) * 64);
#pragma unroll
        for (int k = 0; k < 16; k++)
            op[k] = make_ulonglong2(acc[2 * k], acc[2 * k + 1]);
    }
}

// --------------------------------------------------------------------------
// Kernel 2: ball query -> compacted distinct-pair list
// dynamic smem: 48KB exactly (3 coord arrays)
// --------------------------------------------------------------------------
__global__ void __launch_bounds__(256) k_ballquery(const float* __restrict__ points)
{
    extern __shared__ float sm[];
    float* sx = sm;
    float* sy = sm + NN;
    float* sz = sm + 2 * NN;

    const int b = blockIdx.y;
    const float* px = points + (size_t)b * 3 * NN;
    for (int i = threadIdx.x; i < NN; i += 256) {
        sx[i] = px[i];
        sy[i] = px[NN + i];
        sz[i] = px[2 * NN + i];
    }
    __syncthreads();

    const int w = threadIdx.x >> 5, lane = threadIdx.x & 31;
    const int m = blockIdx.x * 8 + w;
    const int ci = g_cidx[b * MM + m];
    const float cx = sx[ci], cy = sy[ci], cz = sz[ci];
    const float c2 = __fadd_rn(__fadd_rn(__fmul_rn(cx, cx), __fmul_rn(cy, cy)),
                               __fmul_rn(cz, cz));

    // matches JAX: f32(0.04 in f64) — NOT 0.2f*0.2f (1 ulp higher)
    const float RR = (float)(0.2 * 0.2);

    int myn = -1;
    int cnt = 0;
    for (int base = 0; base < NN; base += 32) {
        int n = base + lane;
        float xx = sx[n], yy = sy[n], zz = sz[n];
        float p2 = __fadd_rn(__fadd_rn(__fmul_rn(xx, xx), __fmul_rn(yy, yy)),
                             __fmul_rn(zz, zz));
        float dot = __fadd_rn(__fadd_rn(__fmul_rn(cx, xx), __fmul_rn(cy, yy)),
                              __fmul_rn(cz, zz));
        float d2 = __fsub_rn(__fadd_rn(c2, p2), __fmul_rn(2.0f, dot));
        unsigned msk = __ballot_sync(FULLMASK, d2 <= RR);
        int p = __popc(msk);
        if (lane >= cnt && lane < cnt + p)
            myn = base + (int)__fns(msk, 0, lane - cnt + 1);
        cnt += p;
        if (cnt >= KNN) break;
    }
    int nd = min(cnt, KNN);                    // distinct neighbors (>=1: self)
    int basep = 0;
    if (lane == 0) basep = atomicAdd(&g_pcount, nd);
    basep = __shfl_sync(FULLMASK, basep, 0);
    if (lane < nd)
        g_pairs[basep + lane] = ((unsigned)b << 22) | ((unsigned)m << 12) | (unsigned)myn;
}

// --------------------------------------------------------------------------
// Kernel 3: thread-per-distinct-pair fused MLP; max-pool via atomicMax (relu>=0)
// dynamic smem: 48KB exactly (scaled w2T, w3T)
// --------------------------------------------------------------------------
__global__ void __launch_bounds__(256) k_mlp(
    const float* __restrict__ points,
    const float* __restrict__ w2, const float* __restrict__ g2,
    const float* __restrict__ w3, const float* __restrict__ g3,
    float* __restrict__ d_out)
{
    const int pcount = g_pcount;
    if (blockIdx.x * 256 >= pcount) return;    // no work for this block at all

    extern __shared__ float smf[];             // [0,4096) w2T*s2 ; [4096,12288) w3T*s3
    const int tid = threadIdx.x;
    const float inv = 1.0f / sqrtf(1.0f + 1e-5f);

    for (int i = tid; i < 4096; i += 256) {
        int o = i & 63, c = i >> 6;
        smf[c * 64 + o] = w2[o * 64 + c] * (__ldg(g2 + o) * inv);
    }
    for (int i = tid; i < 8192; i += 256) {
        int o = i & 127, c = i >> 7;
        smf[4096 + c * 128 + o] = w3[o * 64 + c] * (__ldg(g3 + o) * inv);
    }
    __syncthreads();

    const unsigned sb = (unsigned)__cvta_generic_to_shared(smf);
    float* ofeat = d_out + (size_t)BB * 3 * MM;
    const float* cent = d_out;                 // [B,3,M] written by k1

    for (int i = blockIdx.x * 256 + tid; i < pcount; i += gridDim.x * 256) {
        unsigned pr = g_pairs[i];
        const int b = pr >> 22, m = (pr >> 12) & 1023, n = pr & 4095;

        const float* px = points + (size_t)b * 3 * NN;
        const float lx = px[n]          - cent[(size_t)b * 3 * MM + m];
        const float ly = px[NN + n]     - cent[(size_t)b * 3 * MM + MM + m];
        const float lz = px[2 * NN + n] - cent[(size_t)b * 3 * MM + 2 * MM + m];

        // ---- layer 1 (folded constants) ----
        float h1[64];
        {
            const float4* hp = (const float4*)(g_h1f + ((size_t)b * NN + n) * 64);
#pragma unroll
            for (int q = 0; q < 16; q++) {
                float4 v = hp[q];
                h1[4 * q] = v.x; h1[4 * q + 1] = v.y; h1[4 * q + 2] = v.z; h1[4 * q + 3] = v.w;
            }
#pragma unroll
            for (int o4 = 0; o4 < 16; o4++) {
                float4 cb = __ldg(g_l1c + o4);
#pragma unroll
                for (int j = 0; j < 4; j++) {
                    int o = 4 * o4 + j;
                    float4 wv = __ldg(g_l1w + o);
                    float tv = fmaf(h1[o], wv.w, ((const float*)&cb)[j]);
                    tv = fmaf(wv.x, lx, tv);
                    tv = fmaf(wv.y, ly, tv);
                    tv = fmaf(wv.z, lz, tv);
                    h1[o] = fmaxf(tv, 0.0f);
                }
            }
        }

        // ---- layer 2 (packed f32x2, scaled weights) ----
        u64 acc[32];
#pragma unroll
        for (int k = 0; k < 32; k++) acc[k] = 0ULL;
#pragma unroll
        for (int c = 0; c < 64; c++) {
            u64 vv = pk2(h1[c], h1[c]);
            unsigned addr = sb + c * 256;
#pragma unroll
            for (int k = 0; k < 16; k++) {
                u64 wa, wb; lds128(wa, wb, addr + k * 16);
                acc[2 * k]     = fma2p(wa, vv, acc[2 * k]);
                acc[2 * k + 1] = fma2p(wb, vv, acc[2 * k + 1]);
            }
        }
        float h2[64];
#pragma unroll
        for (int k = 0; k < 32; k++) upk2(acc[k], h2[2 * k], h2[2 * k + 1]);
#pragma unroll
        for (int o4 = 0; o4 < 16; o4++) {
            float4 cb = __ldg(g_c2 + o4);
#pragma unroll
            for (int j = 0; j < 4; j++)
                h2[4 * o4 + j] = fmaxf(h2[4 * o4 + j] + ((const float*)&cb)[j], 0.0f);
        }

        // ---- layer 3 (4 chunks of 32 outputs) + atomic max-pool ----
#pragma unroll
        for (int ch = 0; ch < 4; ch++) {
            u64 a2[16];
#pragma unroll
            for (int k = 0; k < 16; k++) a2[k] = 0ULL;
#pragma unroll
            for (int c = 0; c < 64; c++) {
                u64 vv = pk2(h2[c], h2[c]);
                unsigned addr = sb + 16384 + c * 512 + ch * 128;
#pragma unroll
                for (int k = 0; k < 8; k++) {
                    u64 wa, wb; lds128(wa, wb, addr + k * 16);
                    a2[2 * k]     = fma2p(wa, vv, a2[2 * k]);
                    a2[2 * k + 1] = fma2p(wb, vv, a2[2 * k + 1]);
                }
            }
            float v[32];
#pragma unroll
            for (int k = 0; k < 16; k++) upk2(a2[k], v[2 * k], v[2 * k + 1]);
#pragma unroll
            for (int j4 = 0; j4 < 8; j4++) {
                float4 cb = __ldg(g_c3 + ch * 8 + j4);
#pragma unroll
                for (int j = 0; j < 4; j++) {
                    const int o = ch * 32 + 4 * j4 + j;
                    float r = fmaxf(v[4 * j4 + j] + ((const float*)&cb)[j], 0.0f);
                    atomicMax((unsigned*)&ofeat[((size_t)b * 128 + o) * MM + m],
                              __float_as_uint(r));
                }
            }
        }
    }
}

// --------------------------------------------------------------------------
extern "C" void kernel_launch(void* const* d_in, const int* in_sizes, int n_in,
                              void* d_out, int out_size)
{
    const float* points   = (const float*)d_in[0];
    const float* features = (const float*)d_in[1];
    const float* w1  = (const float*)d_in[2];
    const float* b1  = (const float*)d_in[3];
    const float* g1  = (const float*)d_in[4];
    const float* be1 = (const float*)d_in[5];
    const float* w2  = (const float*)d_in[6];
    const float* b2  = (const float*)d_in[7];
    const float* g2  = (const float*)d_in[8];
    const float* be2 = (const float*)d_in[9];
    const float* w3  = (const float*)d_in[10];
    const float* b3  = (const float*)d_in[11];
    const float* g3  = (const float*)d_in[12];
    const float* be3 = (const float*)d_in[13];
    float* out = (float*)d_out;

    // K1: FPS + h1f + output zero + folded constants
    k_fps_h1f<<<BB + 256, 256, 16384>>>(points, features, w1, b1, g1, be1,
                                        b2, g2, be2, b3, g3, be3, out);
    // K2: ball query -> compacted pair list
    k_ballquery<<<dim3(MM / 8, BB), 256, 3 * NN * 4>>>(points);
    // K3: thread-per-pair MLP + atomic max-pool
    k_mlp<<<1024, 256, 12288 * 4>>>(points, w2, g2, w3, g3, out);
}